// round 13
// baseline (speedup 1.0000x reference)
#include <cuda_runtime.h>
#include <cstdint>

// DiverseSiblingsSearch on GB300 — single pass, seg1-sampled threshold, and a
// manually double-buffered filter loop so LDGs stay in flight across the
// atomic-bearing filter (compiler won't hoist loads past atomics itself).
// lprobs: (128, 5, 50257) f32, scores: (128, 5, 10) f32, step: int scalar (=10).
// Output (f32): final_scores (128,10) | final_indices (128,10) | final_beams (128,10).

#define BSZ     128
#define BEAM    5
#define VOCAB   50257
#define KSEL    10
#define ROWS    (BSZ * BEAM)
#define T       256
#define NWARP   (T / 32)
#define NQ1     12                     // seg1 = first NQ1 strided quads/thread = 12288 elems
#define CAP     1024
#define DIV_RATE 0.5f
#define NEG_INF __int_as_float(0xff800000u)
#define IDX_INF 0x7fffffff

// Inter-block scratch (no allocations allowed).
__device__ float g_cand_val[ROWS * KSEL];
__device__ int   g_cand_idx[ROWS * KSEL];
__device__ int   g_batch_done[BSZ];            // zero-init; reset by finisher each replay

__device__ __forceinline__ bool better(float v1, int i1, float v2, int i2) {
    // JAX top_k stability: larger value wins; ties -> smaller index wins.
    return (v1 > v2) || (v1 == v2 && i1 < i2);
}

__device__ __forceinline__ float4 max4(float4 a, float4 b) {
    return make_float4(fmaxf(a.x, b.x), fmaxf(a.y, b.y), fmaxf(a.z, b.z), fmaxf(a.w, b.w));
}

__global__ __launch_bounds__(T, 4)
void dss_kernel(const float* __restrict__ lprobs,
                const float* __restrict__ scores,
                const int* __restrict__ step_ptr,
                int score_last_dim,
                float* __restrict__ out) {
    __shared__ float    swtop[2 * NWARP];       // per-warp top-2 of seg1 per-thread maxima
    __shared__ float    sthr;
    __shared__ unsigned scount;
    __shared__ float    cval[CAP];
    __shared__ int      cidx[CAP];

    const int row   = blockIdx.x;               // row = batch * BEAM + beam
    const int batch = row / BEAM;
    const int tid   = threadIdx.x;
    const int lane  = tid & 31;
    const int wid   = tid >> 5;
    const float* __restrict__ rp = lprobs + (size_t)row * VOCAB;

    if (tid == 0) scount = 0u;

    // Alignment peel: row*VOCAB mod 4 == row mod 4.
    const int P     = (4 - (row & 3)) & 3;      // head elements (scalar)
    const int nv    = (VOCAB - P) >> 2;         // aligned float4 count
    const int tailn = (VOCAB - P) & 3;          // tail elements (scalar)
    const float4* __restrict__ rp4 = reinterpret_cast<const float4*>(rp + P);

    // ---- Phase 1a: branchless max over seg1 (first NQ1 quads/thread) ----
    float4 M0 = make_float4(NEG_INF, NEG_INF, NEG_INF, NEG_INF);
    float4 M1 = M0, M2 = M0, M3 = M0;
#pragma unroll
    for (int j = 0; j < NQ1; j += 4) {
        float4 a = rp4[tid + j * T];
        float4 b = rp4[tid + (j + 1) * T];
        float4 c = rp4[tid + (j + 2) * T];
        float4 d = rp4[tid + (j + 3) * T];
        M0 = max4(M0, a); M1 = max4(M1, b); M2 = max4(M2, c); M3 = max4(M3, d);
    }
    M0 = max4(max4(M0, M1), max4(M2, M3));
    float m = fmaxf(fmaxf(M0.x, M0.y), fmaxf(M0.z, M0.w));

    // ---- Per-warp top-2 of per-thread seg1 maxima (2 distinct elements/warp) ----
    {
        float w1 = m;
        for (int off = 16; off; off >>= 1) w1 = fmaxf(w1, __shfl_xor_sync(0xffffffffu, w1, off));
        unsigned holders = __ballot_sync(0xffffffffu, m == w1);
        int first = __ffs(holders) - 1;
        float m2 = (lane == first) ? NEG_INF : m;
        float w2 = m2;
        for (int off = 16; off; off >>= 1) w2 = fmaxf(w2, __shfl_xor_sync(0xffffffffu, w2, off));
        if (lane == 0) { swtop[wid] = w1; swtop[NWARP + wid] = w2; }
    }
    __syncthreads();

    // ---- thr = 10th largest of 16 distinct seg1 elements.
    // seg1 subset-of row => 10th(sample) <= 10th(row): conservative row-wide. ----
    if (tid < 32) {
        float x = (lane < 2 * NWARP) ? swtop[lane] : NEG_INF;
        float t = NEG_INF;
        for (int r = 0; r < KSEL; ++r) {
            float bv = x;
            for (int off = 16; off; off >>= 1) bv = fmaxf(bv, __shfl_xor_sync(0xffffffffu, bv, off));
            unsigned holders = __ballot_sync(0xffffffffu, x == bv);
            int first = __ffs(holders) - 1;
            if (lane == first) x = NEG_INF;     // retire one instance
            t = bv;
        }
        if (lane == 0) sthr = t;
    }
    __syncthreads();
    const float thr = sthr;

    // Quad filter: prefilter on quad max, push survivors (exact value+index).
    auto filter_quad = [&](float4 a, int i0) {
        float qm = fmaxf(fmaxf(a.x, a.y), fmaxf(a.z, a.w));
        if (qm >= thr) {                        // rare (~0.5% of quads)
            if (a.x >= thr) { unsigned p = atomicAdd(&scount, 1u); if (p < CAP) { cval[p] = a.x; cidx[p] = i0; } }
            if (a.y >= thr) { unsigned p = atomicAdd(&scount, 1u); if (p < CAP) { cval[p] = a.y; cidx[p] = i0 + 1; } }
            if (a.z >= thr) { unsigned p = atomicAdd(&scount, 1u); if (p < CAP) { cval[p] = a.z; cidx[p] = i0 + 2; } }
            if (a.w >= thr) { unsigned p = atomicAdd(&scount, 1u); if (p < CAP) { cval[p] = a.w; cidx[p] = i0 + 3; } }
        }
    };

    // ---- Phase 2: one filtered pass over the ENTIRE row (seg1 hits L1/L2).
    // Double-buffered: batch i+1's 4 LDG.128 issue BEFORE batch i's filter
    // (whose smem atomics would otherwise fence the loads) -> loads always in flight.
    {
        const int STR = 4 * T;
        int va = tid;
        if (va + 3 * T < nv) {
            float4 A0 = rp4[va], A1 = rp4[va + T], A2 = rp4[va + 2 * T], A3 = rp4[va + 3 * T];
            int vn = va + STR;
            for (; vn + 3 * T < nv; vn += STR) {
                float4 B0 = rp4[vn], B1 = rp4[vn + T], B2 = rp4[vn + 2 * T], B3 = rp4[vn + 3 * T];
                filter_quad(A0, P + 4 * va);
                filter_quad(A1, P + 4 * (va + T));
                filter_quad(A2, P + 4 * (va + 2 * T));
                filter_quad(A3, P + 4 * (va + 3 * T));
                A0 = B0; A1 = B1; A2 = B2; A3 = B3; va = vn;
            }
            filter_quad(A0, P + 4 * va);
            filter_quad(A1, P + 4 * (va + T));
            filter_quad(A2, P + 4 * (va + 2 * T));
            filter_quad(A3, P + 4 * (va + 3 * T));
            for (int v2 = vn; v2 < nv; v2 += T) filter_quad(rp4[v2], P + 4 * v2);
        } else {
            for (int v2 = tid; v2 < nv; v2 += T) filter_quad(rp4[v2], P + 4 * v2);
        }
    }
    if (tid == 0) {          // head elements, exact test
        for (int i = 0; i < P; ++i) {
            float x = rp[i];
            if (x >= thr) { unsigned p = atomicAdd(&scount, 1u); if (p < CAP) { cval[p] = x; cidx[p] = i; } }
        }
    }
    if (tid == 1) {          // tail elements, exact test
        for (int q = 0; q < tailn; ++q) {
            int i = P + 4 * nv + q;
            float x = rp[i];
            if (x >= thr) { unsigned p = atomicAdd(&scount, 1u); if (p < CAP) { cval[p] = x; cidx[p] = i; } }
        }
    }
    __syncthreads();

    const unsigned cnt   = scount;
    const int      stepv = step_ptr ? *step_ptr : KSEL;
    const float    base  = scores[row * score_last_dim + (stepv - 1)];

    if (cnt > CAP) {
        // Pathological mass-tie fallback: exact serial top-10.
        if (tid == 0) {
            float val[KSEL]; int idq[KSEL];
#pragma unroll
            for (int q = 0; q < KSEL; ++q) { val[q] = NEG_INF; idq[q] = IDX_INF; }
            for (int i = 0; i < VOCAB; ++i) {
                float x = rp[i];
                if (better(x, i, val[KSEL - 1], idq[KSEL - 1])) {
                    val[KSEL - 1] = x; idq[KSEL - 1] = i;
#pragma unroll
                    for (int q = KSEL - 1; q > 0; --q) {
                        if (better(val[q], idq[q], val[q - 1], idq[q - 1])) {
                            float tv = val[q]; val[q] = val[q - 1]; val[q - 1] = tv;
                            int   ti = idq[q]; idq[q] = idq[q - 1]; idq[q - 1] = ti;
                        }
                    }
                }
            }
#pragma unroll
            for (int r = 0; r < KSEL; ++r) {
                g_cand_val[row * KSEL + r] = (val[r] + base) - (float)(r + 1) * DIV_RATE;
                g_cand_idx[row * KSEL + r] = idq[r];
            }
        }
    } else {
        // Warp-parallel stable top-10 over ~50 exact candidates.
        if (tid < 32) {
            for (int r = 0; r < KSEL; ++r) {
                float bv = NEG_INF; int bi = IDX_INF; int bp = -1;
                for (unsigned c = lane; c < cnt; c += 32) {
                    float x = cval[c]; int ix = cidx[c];
                    if (better(x, ix, bv, bi)) { bv = x; bi = ix; bp = (int)c; }
                }
                for (int off = 16; off; off >>= 1) {
                    float ov = __shfl_down_sync(0xffffffffu, bv, off);
                    int   oi = __shfl_down_sync(0xffffffffu, bi, off);
                    int   op = __shfl_down_sync(0xffffffffu, bp, off);
                    if (better(ov, oi, bv, bi)) { bv = ov; bi = oi; bp = op; }
                }
                if (lane == 0) {
                    // ((lprob + base) - penalty): reference op order -> bit-exact.
                    g_cand_val[row * KSEL + r] = (bv + base) - (float)(r + 1) * DIV_RATE;
                    g_cand_idx[row * KSEL + r] = bi;
                    cval[bp] = NEG_INF; cidx[bp] = IDX_INF;
                }
                __syncwarp();
            }
        }
    }

    // ---- Fused finisher: last beam-block of the batch does the 50->10 select ----
    int done = 0;
    if (tid == 0) {
        __threadfence();                              // release g_cand writes
        done = atomicAdd(&g_batch_done[batch], 1);
    }
    if (tid < 32) {
        done = __shfl_sync(0xffffffffu, done, 0);
        if (done == BEAM - 1) {
            __threadfence();                          // acquire peers' g_cand
            const int b50 = batch * BEAM * KSEL;
            float v0 = NEG_INF, v1 = NEG_INF;
            int   p0 = IDX_INF, p1 = IDX_INF;
            if (lane < BEAM * KSEL)      { v0 = __ldcg(&g_cand_val[b50 + lane]);      p0 = lane; }
            if (lane + 32 < BEAM * KSEL) { v1 = __ldcg(&g_cand_val[b50 + lane + 32]); p1 = lane + 32; }
            for (int r = 0; r < KSEL; ++r) {
                float bv; int bp;
                if (better(v0, p0, v1, p1)) { bv = v0; bp = p0; } else { bv = v1; bp = p1; }
                for (int off = 16; off; off >>= 1) {
                    float ov = __shfl_down_sync(0xffffffffu, bv, off);
                    int   op = __shfl_down_sync(0xffffffffu, bp, off);
                    if (better(ov, op, bv, bp)) { bv = ov; bp = op; }
                }
                bv = __shfl_sync(0xffffffffu, bv, 0);
                bp = __shfl_sync(0xffffffffu, bp, 0);
                if (lane == 0) {
                    out[batch * KSEL + r]                  = bv;                                   // scores
                    out[BSZ * KSEL + batch * KSEL + r]     = (float)__ldcg(&g_cand_idx[b50 + bp]); // indices
                    out[2 * BSZ * KSEL + batch * KSEL + r] = (float)(bp / KSEL);                   // beams
                }
                if (p0 == bp) { v0 = NEG_INF; p0 = IDX_INF; }
                if (p1 == bp) { v1 = NEG_INF; p1 = IDX_INF; }
            }
            if (lane == 0) atomicExch(&g_batch_done[batch], 0);   // reset for next replay
        }
    }
}

extern "C" void kernel_launch(void* const* d_in, const int* in_sizes, int n_in,
                              void* d_out, int out_size) {
    const float* lprobs = (const float*)d_in[0];
    const float* scores = (const float*)d_in[1];
    const int*   step   = (n_in >= 3) ? (const int*)d_in[2] : nullptr;
    const int score_last_dim = in_sizes[1] / ROWS;   // = 10

    dss_kernel<<<ROWS, T>>>(lprobs, scores, step, score_last_dim, (float*)d_out);
}